// round 3
// baseline (speedup 1.0000x reference)
#include <cuda_runtime.h>
#include <math.h>

#define BB 32
#define NN 64
#define KK 128
#define NPAIR (BB*NN*NN)   // 131072
#define NNODE (BB*NN)      // 2048

// ---------------- scratch (no cudaMalloc allowed) ----------------
__device__ float g_rad[NPAIR*8];     // 4 MB
__device__ float g_Y[NPAIR*8];       // 4 MB  (Y1[0..2], Y2[0..4])
__device__ float g_mask[NPAIR];      // 0.5 MB
__device__ float g_h1[NNODE*KK];
__device__ float g_s1[NNODE*KK];
__device__ float g_v1[NNODE*3*KK];
__device__ float g_s2[NNODE*KK];

__device__ __forceinline__ float siluf(float x) { return x / (1.0f + __expf(-x)); }

// ---------------- kernel 1: pairwise geometry ----------------
__global__ void k_geom(const float* __restrict__ frac, const float* __restrict__ cell)
{
    int idx = blockIdx.x * blockDim.x + threadIdx.x;
    if (idx >= NPAIR) return;
    int b = idx >> 12;
    int i = (idx >> 6) & 63;
    int j = idx & 63;
    const float* fi = frac + (b*NN + i)*3;
    const float* fj = frac + (b*NN + j)*3;
    float d0 = fi[0]-fj[0], d1 = fi[1]-fj[1], d2 = fi[2]-fj[2];
    d0 -= rintf(d0); d1 -= rintf(d1); d2 -= rintf(d2);
    const float* C = cell + b*9;
    float x = d0*C[0] + d1*C[3] + d2*C[6];
    float y = d0*C[1] + d1*C[4] + d2*C[7];
    float z = d0*C[2] + d1*C[5] + d2*C[8];
    float r2 = fmaxf(x*x + y*y + z*z, 1e-12f);
    float r = sqrtf(r2);
    bool m = (r < 5.0f) && (i != j);
    float mf = m ? 1.0f : 0.0f;
    float rs = m ? r : 1.0f;
    float inv = 1.0f / rs;
    float ux = x*inv*mf, uy = y*inv*mf, uz = z*inv*mf;
    // cutoff polynomial p=5: fc = 1 - 21u^5 + 35u^6 - 15u^7
    float u = rs * 0.2f;
    float u2 = u*u, u4 = u2*u2, u5 = u4*u;
    float fc = 1.0f - 21.0f*u5 + 35.0f*u5*u - 15.0f*u5*u2;
    fc = (u < 1.0f) ? fc : 0.0f;
    float pref = 0.6324555320336759f * inv * fc * mf;   // sqrt(2/5)
    float w = 0.6283185307179586f * rs;                  // pi/5 * r
    float* rp = g_rad + (size_t)idx*8;
    #pragma unroll
    for (int n = 1; n <= 8; ++n) rp[n-1] = pref * sinf((float)n * w);
    const float s3 = 1.7320508075688772f, s5 = 2.23606797749979f, s15 = 3.872983346207417f;
    float* Y = g_Y + (size_t)idx*8;
    Y[0] = s3*ux; Y[1] = s3*uy; Y[2] = s3*uz;
    Y[3] = s15*ux*uy;
    Y[4] = s15*uy*uz;
    Y[5] = 0.5f*s5*(3.0f*uz*uz - 1.0f);
    Y[6] = s15*ux*uz;
    Y[7] = 0.5f*s15*(ux*ux - uy*uy);
    g_mask[idx] = mf;
}

// ---------------- shared 64-wide dense layer (silu) ----------------
// In: [64][ldi] smem, Wsh: [CDIM][64] smem, Out: [64][64] smem.  128 threads.
template<int CDIM>
__device__ __forceinline__ void dense_layer(const float* __restrict__ In, int ldi,
                                            const float* __restrict__ Wsh,
                                            const float* __restrict__ bias,
                                            float* __restrict__ Out, int t)
{
    #pragma unroll 1
    for (int it = 0; it < 8; ++it) {
        int j  = (t >> 4) + 8*it;
        int h0 = (t & 15) * 4;
        float a0 = bias[h0+0], a1 = bias[h0+1], a2 = bias[h0+2], a3 = bias[h0+3];
        const float* inj = In + j*ldi;
        #pragma unroll 4
        for (int c = 0; c < CDIM; ++c) {
            float av = inj[c];
            float4 wv = *(const float4*)(Wsh + c*64 + h0);
            a0 += av*wv.x; a1 += av*wv.y; a2 += av*wv.z; a3 += av*wv.w;
        }
        float4 o4;
        o4.x = siluf(a0); o4.y = siluf(a1); o4.z = siluf(a2); o4.w = siluf(a3);
        *(float4*)(Out + j*64 + h0) = o4;
    }
}

// ---------------- kernel 2: phase 1 (r1 MLP + messages + s1/v1/h1) ----------------
// block = node (b*64+i), 128 threads
__global__ void __launch_bounds__(128) k_phase1(
    const float* __restrict__ w_embed,
    const float* __restrict__ r1_w0, const float* __restrict__ r1_b0,
    const float* __restrict__ r1_w1, const float* __restrict__ r1_b1,
    const float* __restrict__ r1_w2, const float* __restrict__ r1_b2,
    const float* __restrict__ r1_w3, const float* __restrict__ r1_b3,
    const float* __restrict__ mix_l0, const float* __restrict__ mix_l1,
    const float* __restrict__ mix_l2)
{
    extern __shared__ float sm[];
    float* Xin = sm;            // 512
    float* Ysm = Xin + 512;     // 512 (mask premultiplied)
    float* mk  = Ysm + 512;     // 64
    float* Ha  = mk + 64;       // 4096
    float* Hb  = Ha + 4096;     // 4096
    float* Wb  = Hb + 4096;     // 4096
    float* G   = Wb + 4096;     // 576
    float* S   = G + 576;       // 16
    float* msg = S + 16;        // 1152
    float* t2  = msg + 1152;    // 128  -> total 15248 floats (60.99 KB)

    int t = threadIdx.x;
    int node = blockIdx.x;
    int pbase = node * 64;

    for (int idx = t; idx < 512; idx += 128) Xin[idx] = g_rad[(size_t)pbase*8 + idx];
    for (int idx = t; idx < 512; idx += 128)
        Ysm[idx] = g_Y[(size_t)pbase*8 + idx] * g_mask[pbase + (idx >> 3)];
    if (t < 64) mk[t] = g_mask[pbase + t];
    for (int idx = t; idx < 512; idx += 128) Wb[idx] = r1_w0[idx];
    __syncthreads();

    dense_layer<8>(Xin, 8, Wb, r1_b0, Ha, t);
    __syncthreads();
    for (int idx = t; idx < 4096; idx += 128) Wb[idx] = r1_w1[idx];
    __syncthreads();
    dense_layer<64>(Ha, 64, Wb, r1_b1, Hb, t);
    __syncthreads();
    for (int idx = t; idx < 4096; idx += 128) Wb[idx] = r1_w2[idx];
    __syncthreads();
    dense_layer<64>(Hb, 64, Wb, r1_b2, Ha, t);   // final H in Ha
    __syncthreads();

    // G[m][c] = sum_j maskY_m(j) * H[j][c] ;  m: 0=mask(Y0), 1..3=Y1, 4..8=Y2
    for (int idx = t; idx < 576; idx += 128) {
        int m = idx >> 6, c = idx & 63;
        float acc = 0.0f;
        #pragma unroll 8
        for (int j = 0; j < 64; ++j) {
            float yv = (m == 0) ? mk[j] : Ysm[j*8 + m - 1];
            acc += yv * Ha[j*64 + c];
        }
        G[idx] = acc;
    }
    if (t < 9) {
        float acc = 0.0f;
        for (int j = 0; j < 64; ++j) acc += (t == 0) ? mk[j] : Ysm[j*8 + t - 1];
        S[t] = acc;
    }
    __syncthreads();

    // msg[m][k] = (w_embed[k]/16)*(b3[o]*S[m] + sum_c G[m][c]*W3[c][o])
    {
        int k = t;
        float wk = w_embed[k] * 0.0625f;
        #pragma unroll 1
        for (int m = 0; m < 9; ++m) {
            int o = k + ((m == 0) ? 0 : ((m <= 3) ? 128 : 256));
            float acc = r1_b3[o] * S[m];
            const float* Gm = G + m*64;
            #pragma unroll 8
            for (int c = 0; c < 64; ++c) acc += Gm[c] * r1_w3[c*384 + o];
            msg[m*128 + k] = acc * wk;
        }
    }
    __syncthreads();
    {
        float a4 = msg[4*128+t], a5 = msg[5*128+t], a6 = msg[6*128+t],
              a7 = msg[7*128+t], a8 = msg[8*128+t];
        t2[t] = a4*a4 + a5*a5 + a6*a6 + a7*a7 + a8*a8;
    }
    __syncthreads();

    // s1 = msg0 @ l0 + t2 @ l2 ; v1[m] = msg1[m] @ l1 ; h1 = silu(s1)
    {
        int k = t;
        float s = 0.0f;
        #pragma unroll 4
        for (int c = 0; c < 128; ++c)
            s += msg[c]*mix_l0[c*128 + k] + t2[c]*mix_l2[c*128 + k];
        g_s1[node*128 + k] = s;
        g_h1[node*128 + k] = siluf(s);
        #pragma unroll
        for (int m = 0; m < 3; ++m) {
            float v = 0.0f;
            const float* mm = msg + (m+1)*128;
            #pragma unroll 4
            for (int c = 0; c < 128; ++c) v += mm[c]*mix_l1[c*128 + k];
            g_v1[(node*3 + m)*128 + k] = v;
        }
    }
}

// ---------------- kernel 3: phase 2 (r2 MLP + msg_a/msg_b + s2) ----------------
__global__ void __launch_bounds__(128) k_phase2(
    const float* __restrict__ r2_w0, const float* __restrict__ r2_b0,
    const float* __restrict__ r2_w1, const float* __restrict__ r2_b1,
    const float* __restrict__ r2_w2, const float* __restrict__ r2_b2,
    const float* __restrict__ r2_w3, const float* __restrict__ r2_b3,
    const float* __restrict__ mix2)
{
    extern __shared__ float sm[];
    float* Xin  = sm;            // 512
    float* mk   = Xin + 512;     // 64
    float* Y1s  = mk + 64;       // 192 (mask premultiplied)
    float* Ha   = Y1s + 192;     // 4096
    float* Hb   = Ha + 4096;     // 4096
    float* Wb   = Hb + 4096;     // 4096
    float* msgS = Wb + 4096;     // 128  -> 13184 floats (52.7 KB)

    int t = threadIdx.x;
    int node = blockIdx.x;
    int b = node >> 6;
    int pbase = node * 64;

    for (int idx = t; idx < 512; idx += 128) Xin[idx] = g_rad[(size_t)pbase*8 + idx];
    if (t < 64) mk[t] = g_mask[pbase + t];
    for (int idx = t; idx < 192; idx += 128) {
        int j = idx / 3, m = idx - j*3;
        Y1s[idx] = g_Y[(size_t)pbase*8 + j*8 + m] * g_mask[pbase + j];
    }
    for (int idx = t; idx < 512; idx += 128) Wb[idx] = r2_w0[idx];
    __syncthreads();

    dense_layer<8>(Xin, 8, Wb, r2_b0, Ha, t);
    __syncthreads();
    for (int idx = t; idx < 4096; idx += 128) Wb[idx] = r2_w1[idx];
    __syncthreads();
    dense_layer<64>(Ha, 64, Wb, r2_b1, Hb, t);
    __syncthreads();
    for (int idx = t; idx < 4096; idx += 128) Wb[idx] = r2_w2[idx];
    __syncthreads();
    dense_layer<64>(Hb, 64, Wb, r2_b2, Ha, t);   // final H' in Ha
    __syncthreads();

    int k = t;
    float P[64];
    float acc_a, acc_b;
    // msg_a: sum_j mask*we2_0[j,k]*h1[j,k], fused through layer 3
    {
        float sp = 0.0f;
        #pragma unroll
        for (int j = 0; j < 64; ++j) {
            float p = mk[j] * g_h1[(b*64 + j)*128 + k];
            P[j] = p; sp += p;
        }
        float acc = r2_b3[k] * sp;
        #pragma unroll 1
        for (int c = 0; c < 64; c += 4) {
            float s0 = 0.0f, s1 = 0.0f, s2 = 0.0f, s3 = 0.0f;
            #pragma unroll
            for (int j = 0; j < 64; ++j) {
                float4 hv = *(const float4*)(Ha + j*64 + c);
                float pj = P[j];
                s0 += pj*hv.x; s1 += pj*hv.y; s2 += pj*hv.z; s3 += pj*hv.w;
            }
            acc += s0*r2_w3[(c+0)*256 + k] + s1*r2_w3[(c+1)*256 + k]
                 + s2*r2_w3[(c+2)*256 + k] + s3*r2_w3[(c+3)*256 + k];
        }
        acc_a = acc;
    }
    // msg_b: inv[j,k] = sum_m Y1[j,m]*v1[j,m,k] (mask folded into Y1s)
    {
        float sq = 0.0f;
        #pragma unroll
        for (int j = 0; j < 64; ++j) {
            const float* vp = g_v1 + ((size_t)(b*64 + j)*3)*128 + k;
            float q = Y1s[j*3+0]*vp[0] + Y1s[j*3+1]*vp[128] + Y1s[j*3+2]*vp[256];
            P[j] = q; sq += q;
        }
        float acc = r2_b3[128 + k] * sq;
        #pragma unroll 1
        for (int c = 0; c < 64; c += 4) {
            float s0 = 0.0f, s1 = 0.0f, s2 = 0.0f, s3 = 0.0f;
            #pragma unroll
            for (int j = 0; j < 64; ++j) {
                float4 hv = *(const float4*)(Ha + j*64 + c);
                float pj = P[j];
                s0 += pj*hv.x; s1 += pj*hv.y; s2 += pj*hv.z; s3 += pj*hv.w;
            }
            acc += s0*r2_w3[(c+0)*256 + 128 + k] + s1*r2_w3[(c+1)*256 + 128 + k]
                 + s2*r2_w3[(c+2)*256 + 128 + k] + s3*r2_w3[(c+3)*256 + 128 + k];
        }
        acc_b = acc;
    }
    msgS[k] = (acc_a + acc_b) * 0.0625f;
    __syncthreads();
    float s2v = 0.0f;
    #pragma unroll 4
    for (int c = 0; c < 128; ++c) s2v += msgS[c] * mix2[c*128 + k];
    g_s2[node*128 + k] = s2v;
}

// ---------------- kernel 4: final MLP (16 nodes per block) ----------------
#define XS_LD 644    // padded row stride (16B aligned)
__global__ void __launch_bounds__(512) k_mlp(
    const float* __restrict__ tim,
    const float* __restrict__ w0, const float* __restrict__ b0,
    const float* __restrict__ w1, const float* __restrict__ b1,
    const float* __restrict__ w2, const float* __restrict__ b2,
    float* __restrict__ out)
{
    extern __shared__ float sm[];
    float* xs  = sm;               // 16*644 = 10304
    float* h0s = xs + 16*XS_LD;    // 16*512 = 8192
    float* h1s = xs;               // overlays xs after layer0

    int t = threadIdx.x;
    int rbase = blockIdx.x * 16;

    for (int idx = t; idx < 16*641; idx += 512) {
        int r = idx / 641, c = idx - r*641;
        int node = rbase + r;
        float v;
        if (c < 128)       v = g_s1[node*128 + c];
        else if (c < 512)  v = g_v1[(size_t)node*384 + (c - 128)];
        else if (c < 640)  v = g_s2[node*128 + (c - 512)];
        else               v = tim[node >> 6];
        xs[r*XS_LD + c] = v;
    }
    __syncthreads();

    // layer 0: 641 -> 512, relu
    {
        float acc[16];
        float bb = b0[t];
        #pragma unroll
        for (int r = 0; r < 16; ++r) acc[r] = bb;
        #pragma unroll 1
        for (int c = 0; c < 640; c += 4) {
            float wv0 = w0[(c+0)*512 + t];
            float wv1 = w0[(c+1)*512 + t];
            float wv2 = w0[(c+2)*512 + t];
            float wv3 = w0[(c+3)*512 + t];
            #pragma unroll
            for (int r = 0; r < 16; ++r) {
                float4 xv = *(const float4*)(xs + r*XS_LD + c);
                acc[r] += xv.x*wv0 + xv.y*wv1 + xv.z*wv2 + xv.w*wv3;
            }
        }
        float wl = w0[640*512 + t];
        #pragma unroll
        for (int r = 0; r < 16; ++r) acc[r] += xs[r*XS_LD + 640] * wl;
        #pragma unroll
        for (int r = 0; r < 16; ++r) h0s[r*512 + t] = fmaxf(acc[r], 0.0f);
    }
    __syncthreads();

    // layer 1: 512 -> 512, relu (writes h1s overlaying xs)
    {
        float acc[16];
        float bb = b1[t];
        #pragma unroll
        for (int r = 0; r < 16; ++r) acc[r] = bb;
        #pragma unroll 1
        for (int c = 0; c < 512; c += 4) {
            float wv0 = w1[(c+0)*512 + t];
            float wv1 = w1[(c+1)*512 + t];
            float wv2 = w1[(c+2)*512 + t];
            float wv3 = w1[(c+3)*512 + t];
            #pragma unroll
            for (int r = 0; r < 16; ++r) {
                float4 hv = *(const float4*)(h0s + r*512 + c);
                acc[r] += hv.x*wv0 + hv.y*wv1 + hv.z*wv2 + hv.w*wv3;
            }
        }
        #pragma unroll
        for (int r = 0; r < 16; ++r) h1s[r*512 + t] = fmaxf(acc[r], 0.0f);
    }
    __syncthreads();

    // layer 2: 512 -> 3 ; warp w handles row r = w
    {
        int wid = t >> 5, lane = t & 31;
        int r = wid;
        float p0 = 0.0f, p1 = 0.0f, p2 = 0.0f;
        for (int c = lane; c < 512; c += 32) {
            float hv = h1s[r*512 + c];
            p0 += hv * w2[c*3 + 0];
            p1 += hv * w2[c*3 + 1];
            p2 += hv * w2[c*3 + 2];
        }
        #pragma unroll
        for (int off = 16; off > 0; off >>= 1) {
            p0 += __shfl_down_sync(0xffffffffu, p0, off);
            p1 += __shfl_down_sync(0xffffffffu, p1, off);
            p2 += __shfl_down_sync(0xffffffffu, p2, off);
        }
        if (lane == 0) {
            int node = rbase + r;
            out[node*3 + 0] = p0 + b2[0];
            out[node*3 + 1] = p1 + b2[1];
            out[node*3 + 2] = p2 + b2[2];
        }
    }
}

// ---------------- launch ----------------
extern "C" void kernel_launch(void* const* d_in, const int* in_sizes, int n_in,
                              void* d_out, int out_size)
{
    const float* frac    = (const float*)d_in[0];
    const float* tim     = (const float*)d_in[1];
    const float* cell    = (const float*)d_in[2];
    const float* w_embed = (const float*)d_in[3];
    const float* r1_w0 = (const float*)d_in[4];
    const float* r1_b0 = (const float*)d_in[5];
    const float* r1_w1 = (const float*)d_in[6];
    const float* r1_b1 = (const float*)d_in[7];
    const float* r1_w2 = (const float*)d_in[8];
    const float* r1_b2 = (const float*)d_in[9];
    const float* r1_w3 = (const float*)d_in[10];
    const float* r1_b3 = (const float*)d_in[11];
    const float* mix1_l0 = (const float*)d_in[12];
    const float* mix1_l1 = (const float*)d_in[13];
    const float* mix1_l2 = (const float*)d_in[14];
    const float* r2_w0 = (const float*)d_in[15];
    const float* r2_b0 = (const float*)d_in[16];
    const float* r2_w1 = (const float*)d_in[17];
    const float* r2_b1 = (const float*)d_in[18];
    const float* r2_w2 = (const float*)d_in[19];
    const float* r2_b2 = (const float*)d_in[20];
    const float* r2_w3 = (const float*)d_in[21];
    const float* r2_b3 = (const float*)d_in[22];
    const float* mix2  = (const float*)d_in[23];
    const float* mlp_w0 = (const float*)d_in[24];
    const float* mlp_b0 = (const float*)d_in[25];
    const float* mlp_w1 = (const float*)d_in[26];
    const float* mlp_b1 = (const float*)d_in[27];
    const float* mlp_w2 = (const float*)d_in[28];
    const float* mlp_b2 = (const float*)d_in[29];

    const int SM_P1  = 15248 * 4;
    const int SM_P2  = 13184 * 4;
    const int SM_MLP = (16*XS_LD + 16*512) * 4;

    cudaFuncSetAttribute(k_phase1, cudaFuncAttributeMaxDynamicSharedMemorySize, SM_P1);
    cudaFuncSetAttribute(k_phase2, cudaFuncAttributeMaxDynamicSharedMemorySize, SM_P2);
    cudaFuncSetAttribute(k_mlp,    cudaFuncAttributeMaxDynamicSharedMemorySize, SM_MLP);

    k_geom<<<NPAIR/256, 256>>>(frac, cell);
    k_phase1<<<NNODE, 128, SM_P1>>>(w_embed,
        r1_w0, r1_b0, r1_w1, r1_b1, r1_w2, r1_b2, r1_w3, r1_b3,
        mix1_l0, mix1_l1, mix1_l2);
    k_phase2<<<NNODE, 128, SM_P2>>>(
        r2_w0, r2_b0, r2_w1, r2_b1, r2_w2, r2_b2, r2_w3, r2_b3, mix2);
    k_mlp<<<NNODE/16, 512, SM_MLP>>>(tim, mlp_w0, mlp_b0, mlp_w1, mlp_b1,
        mlp_w2, mlp_b2, (float*)d_out);
}